// round 4
// baseline (speedup 1.0000x reference)
#include <cuda_runtime.h>
#include <cuda_bf16.h>

#define T_STEPS 131072

static __device__ __constant__ const float kDT  = (float)(1.0 / 262.0);
#define ETA_F     1e-6f
#define TWO_ETA_F 2e-6f

// Packed per-step inputs: {obs, kap*softplus(theta+garch), carma0, carma1}
__device__ float4 g_pack[T_STEPS];

__global__ void pack_kernel(const float* __restrict__ obs,
                            const float* __restrict__ garch,
                            const float* __restrict__ carma,
                            const float* __restrict__ kappa,
                            const float* __restrict__ theta) {
    int t = blockIdx.x * blockDim.x + threadIdx.x;
    if (t < T_STEPS) {
        float kap = log1pf(expf(kappa[0]));
        float th  = log1pf(expf(theta[0] + garch[t]));
        g_pack[t] = make_float4(obs[t], kap * th, carma[2 * t], carma[2 * t + 1]);
    }
}

__global__ void __launch_bounds__(32, 1) scan_kernel(
    const float* __restrict__ w0v, const float* __restrict__ P0,
    const float* __restrict__ b0p, const float* __restrict__ b1p,
    const float* __restrict__ a1p, const float* __restrict__ kappap,
    const float* __restrict__ xip, const float* __restrict__ rhop,
    float4* __restrict__ out) {
    if (threadIdx.x != 0) return;

    const float DT   = kDT;
    float kap  = log1pf(expf(kappap[0]));
    float xi_  = log1pf(expf(xip[0]));
    float rho_ = tanhf(rhop[0]);
    float xi2  = xi_ * xi_;
    float xr   = xi_ * rho_;
    float a1   = a1p[0];
    float f1   = b0p[0] * DT;
    float f2   = b1p[0] * DT;
    float dd   = 1.0f - a1 * DT;
    float C0   = 0.5f * xi2 - kap;

    // State
    float w0 = w0v[0], w1 = w0v[1], w2 = w0v[2];
    float p00 = P0[0], p01 = P0[1], p02 = P0[2];
    float p11 = P0[4], p12 = P0[5], p22 = P0[8];

    // Software-pipelined input ring (prefetch depth 8)
    float4 buf[8];
#pragma unroll
    for (int i = 0; i < 8; i++) buf[i] = g_pack[i];

    for (int t = 0; t < T_STEPS; t += 8) {
#pragma unroll
        for (int j = 0; j < 8; j++) {
            float4 d = buf[j];
            int nt = t + 8 + j;
            if (nt < T_STEPS) buf[j] = g_pack[nt];

            float obs = d.x, kth = d.y, c0 = d.z, c1 = d.w;

            // --- predict ---
            float en   = __expf(-w0);          // exp(-w0)
            float sg   = __expf(0.5f * w0);    // sigma
            float term = kth * fminf(en, 1.0f);
            float a    = 1.0f - term;
            float sigma2 = sg * sg;
            float cross  = sg * xr;

            float w0p = fmaf(term + C0, DT, w0);
            float w1p = fmaf(w2 + c0, DT, w1);
            float w2p = fmaf(fmaf(-a1, w2, c1), DT, w2);

            // P_pred (symmetric 6 elems); Psi = diag(a,1,dd) + Psi[1,2]=DT
            float p00p = fmaf(a * a, p00, fmaf(xi2, DT, TWO_ETA_F));
            float p01p = a * fmaf(DT, p02, p01);
            float p02p = fmaf(a * dd, p02, cross * DT);
            float t11  = fmaf(DT, p22, p12 + p12);
            float p11p = fmaf(DT, t11, p11) + TWO_ETA_F;
            float p12p = dd * fmaf(DT, p22, p12);
            float p22p = fmaf(dd * dd, p22, fmaf(sigma2, DT, TWO_ETA_F));

            // --- update ---
            float sig2p = __expf(w0p);
            float u0 = fmaf(f1, p01p, f2 * p02p);   // u = P_pred @ phi_row
            float u1 = fmaf(f1, p11p, f2 * p12p);
            float u2 = fmaf(f1, p12p, f2 * p22p);
            float Q  = fmaf(f1, u1, fmaf(f2, u2, fmaf(sig2p, DT, TWO_ETA_F)));
            float rq = __fdividef(1.0f, Q);

            float xp    = fmaf(f1, w1p, f2 * w2p);
            float innov = obs - xp;
            float g     = innov * rq;

            w0 = fmaf(u0, g, w0p);
            w1 = fmaf(u1, g, w1p);
            w2 = fmaf(u2, g, w2p);

            float s0 = u0 * rq, s1 = u1 * rq, s2 = u2 * rq;
            p00 = fmaf(-s0, u0, p00p) + ETA_F;
            p01 = fmaf(-s0, u1, p01p);
            p02 = fmaf(-s0, u2, p02p);
            p11 = fmaf(-s1, u1, p11p) + ETA_F;
            p12 = fmaf(-s1, u2, p12p);
            p22 = fmaf(-s2, u2, p22p) + ETA_F;

            out[t + j] = make_float4(xp, w0, w1, w2);
        }
    }
}

extern "C" void kernel_launch(void* const* d_in, const int* in_sizes, int n_in,
                              void* d_out, int out_size) {
    const float* obs   = (const float*)d_in[0];
    const float* garch = (const float*)d_in[1];
    const float* carma = (const float*)d_in[2];
    const float* w0v   = (const float*)d_in[3];
    const float* P0    = (const float*)d_in[4];
    const float* b0    = (const float*)d_in[5];
    const float* b1    = (const float*)d_in[6];
    const float* a1    = (const float*)d_in[7];
    const float* kappa = (const float*)d_in[8];
    const float* theta = (const float*)d_in[9];
    const float* xi    = (const float*)d_in[10];
    const float* rho   = (const float*)d_in[11];
    float4* out = (float4*)d_out;

    pack_kernel<<<(T_STEPS + 255) / 256, 256>>>(obs, garch, carma, kappa, theta);
    scan_kernel<<<1, 32>>>(w0v, P0, b0, b1, a1, kappa, xi, rho, out);
}

// round 5
// speedup vs baseline: 1.6851x; 1.6851x over previous
#include <cuda_runtime.h>
#include <cuda_bf16.h>

#define T_STEPS 131072

static __device__ __constant__ const float kDT  = (float)(1.0 / 262.0);
#define ETA_F     1e-6f
#define TWO_ETA_F 2e-6f

// Packed per-step inputs: {obs, kap*softplus(theta+garch), carma0, carma1}
__device__ float4 g_pack[T_STEPS];

__global__ void pack_kernel(const float* __restrict__ obs,
                            const float* __restrict__ garch,
                            const float* __restrict__ carma,
                            const float* __restrict__ kappa,
                            const float* __restrict__ theta) {
    int t = blockIdx.x * blockDim.x + threadIdx.x;
    if (t < T_STEPS) {
        float kap = log1pf(expf(kappa[0]));
        float th  = log1pf(expf(theta[0] + garch[t]));
        g_pack[t] = make_float4(obs[t], kap * th, carma[2 * t], carma[2 * t + 1]);
    }
}

__global__ void __launch_bounds__(32, 1) scan_kernel(
    const float* __restrict__ w0v, const float* __restrict__ P0,
    const float* __restrict__ b0p, const float* __restrict__ b1p,
    const float* __restrict__ a1p, const float* __restrict__ kappap,
    const float* __restrict__ xip, const float* __restrict__ rhop,
    float4* __restrict__ out) {
    if (threadIdx.x != 0) return;

    const float DT   = kDT;
    float kap  = log1pf(expf(kappap[0]));
    float xi_  = log1pf(expf(xip[0]));
    float rho_ = tanhf(rhop[0]);
    float xi2  = xi_ * xi_;
    float a1   = a1p[0];
    float f1   = b0p[0] * DT;
    float f2   = b1p[0] * DT;
    float dd   = 1.0f - a1 * DT;
    float ddsq = dd * dd;
    float C0DT = (0.5f * xi2 - kap) * DT;     // (xi^2/2 - kap)*DT
    float R00c = fmaf(xi2, DT, TWO_ETA_F);    // xi^2*DT + 2eta
    float xrDT = xi_ * rho_ * DT;             // cross*DT = S * xrDT

    // State
    float w0 = w0v[0], w1 = w0v[1], w2 = w0v[2];
    float p00 = P0[0], p01 = P0[1], p02 = P0[2];
    float p11 = P0[4], p12 = P0[5], p22 = P0[8];

    // Carried exponentials of w0 (updated by cubic/quadratic Taylor per step,
    // refreshed exactly every 1024 steps) and carried 1/Q (Newton-updated).
    float E  = __expf(w0);          // exp(w0)   (= sigma^2)
    float En = __expf(-w0);         // exp(-w0)
    float S  = __expf(0.5f * w0);   // exp(w0/2) (= sigma)
    float rq = 1.0f / fmaf(E, DT, TWO_ETA_F);   // seed ~ 1/Q; Newton corrects

    // Software-pipelined input ring (prefetch depth 8)
    float4 buf[8];
#pragma unroll
    for (int i = 0; i < 8; i++) buf[i] = g_pack[i];

    for (int t = 0; t < T_STEPS; t += 8) {
        if ((t & 1023) == 0) {      // periodic exact resync (kills poly drift)
            E  = __expf(w0);
            En = __expf(-w0);
            S  = __expf(0.5f * w0);
        }
#pragma unroll
        for (int j = 0; j < 8; j++) {
            float4 d = buf[j];
            int nt = t + 8 + j;
            if (nt < T_STEPS) buf[j] = g_pack[nt];

            float obs = d.x, kth = d.y, c0 = d.z, c1 = d.w;

            // --- predict ---
            float term = fminf(kth * En, kth);        // kth*clip(exp(-w0),0,1)
            float dw1  = fmaf(term, DT, C0DT);        // (term + C0)*DT
            float a    = 1.0f - term;

            float w0p = w0 + dw1;
            float w1p = fmaf(w2 + c0, DT, w1);
            float w2p = fmaf(fmaf(-a1, w2, c1), DT, w2);

            // P_pred (symmetric 6 elems); Psi = diag(a,1,dd) + Psi[1,2]=DT
            float p00p = fmaf(a * a, p00, R00c);
            float p01p = a * fmaf(DT, p02, p01);
            float p02p = fmaf(a * dd, p02, S * xrDT);
            float t11  = fmaf(DT, p22, p12 + p12);
            float p11p = fmaf(DT, t11, p11) + TWO_ETA_F;
            float p12p = dd * fmaf(DT, p22, p12);
            float p22p = fmaf(ddsq, p22, fmaf(E, DT, TWO_ETA_F));

            // --- update ---
            // sig2p = exp(w0p) = E * (1 + dw1 + dw1^2/2), |dw1| <~ 2e-3
            float sig2p = E * fmaf(dw1, fmaf(dw1, 0.5f, 1.0f), 1.0f);
            float u0 = fmaf(f1, p01p, f2 * p02p);     // u = P_pred @ phi_row
            float u1 = fmaf(f1, p11p, f2 * p12p);
            float u2 = fmaf(f1, p12p, f2 * p22p);
            float Q  = fmaf(f1, u1, fmaf(f2, u2, fmaf(sig2p, DT, TWO_ETA_F)));
            rq = rq * fmaf(-Q, rq, 2.0f);             // Newton: rq <- rq(2-Q*rq)

            float xp    = fmaf(f1, w1p, f2 * w2p);
            float g     = (obs - xp) * rq;

            w0 = fmaf(u0, g, w0p);
            w1 = fmaf(u1, g, w1p);
            w2 = fmaf(u2, g, w2p);

            float s0 = u0 * rq, s1 = u1 * rq, s2 = u2 * rq;
            p00 = fmaf(-s0, u0, p00p) + ETA_F;
            p01 = fmaf(-s0, u1, p01p);
            p02 = fmaf(-s0, u2, p02p);
            p11 = fmaf(-s1, u1, p11p) + ETA_F;
            p12 = fmaf(-s1, u2, p12p);
            p22 = fmaf(-s2, u2, p22p) + ETA_F;

            // --- carried exponentials: multiply by exp(+/-dw) Taylor ---
            float dw   = fmaf(u0, g, dw1);            // w0_post - w0_prev
            float dw2  = dw * dw;
            float even = fmaf(dw2, 0.5f, 1.0f);                 // 1 + dw^2/2
            float odd  = dw * fmaf(dw2, 0.16666667f, 1.0f);     // dw + dw^3/6
            E  = E  * (even + odd);
            En = En * (even - odd);
            S  = S  * fmaf(dw, fmaf(dw, 0.125f, 0.5f), 1.0f);   // exp(dw/2)

            out[t + j] = make_float4(xp, w0, w1, w2);
        }
    }
}

extern "C" void kernel_launch(void* const* d_in, const int* in_sizes, int n_in,
                              void* d_out, int out_size) {
    const float* obs   = (const float*)d_in[0];
    const float* garch = (const float*)d_in[1];
    const float* carma = (const float*)d_in[2];
    const float* w0v   = (const float*)d_in[3];
    const float* P0    = (const float*)d_in[4];
    const float* b0    = (const float*)d_in[5];
    const float* b1    = (const float*)d_in[6];
    const float* a1    = (const float*)d_in[7];
    const float* kappa = (const float*)d_in[8];
    const float* theta = (const float*)d_in[9];
    const float* xi    = (const float*)d_in[10];
    const float* rho   = (const float*)d_in[11];
    float4* out = (float4*)d_out;

    pack_kernel<<<(T_STEPS + 255) / 256, 256>>>(obs, garch, carma, kappa, theta);
    scan_kernel<<<1, 32>>>(w0v, P0, b0, b1, a1, kappa, xi, rho, out);
}